// round 5
// baseline (speedup 1.0000x reference)
#include <cuda_runtime.h>

// SoftRank via bucket-histogram rank + windowed exact sigmoid, with
// sorted-position thread reassignment for a divergence-free epilogue.
//
// out[b,j,c] = (1/N) * sum_i sigmoid(1000*(x[b,j,c]-x[b,i,c]))
//
// Per (b,c) column:
//   1. histogram 1024 values into 1024 buckets over [-5,5]
//   2. block exclusive prefix sum (1 bucket/thread)
//   3. scatter (value, original index) into bucket order
//   4. thread t evaluates SORTED element t: rank from bucket prefix,
//      tanh window scan (tanh.approx saturates -> branchless & exact)

#define NN       1024
#define CC       16
#define BB       8
#define NBKT     1024
#define RANGE_LO (-5.0f)
#define INV_W    102.4f          // NBKT / 10.0
#define WINDOW   0.009f          // |500*2*(v-s)| <= 9 outside -> tail ~1.2e-4

__device__ __forceinline__ float fast_tanh(float x) {
    float r;
    asm("tanh.approx.f32 %0, %1;" : "=f"(r) : "f"(x));
    return r;
}

__device__ __forceinline__ int bucket_of(float v) {
    int b = (int)((v - RANGE_LO) * INV_W);
    return min(max(b, 0), NBKT - 1);
}

__global__ __launch_bounds__(NN) void softrank_bucket2_kernel(
    const float* __restrict__ x, float* __restrict__ out)
{
    const int b = blockIdx.x >> 4;       // / CC
    const int c = blockIdx.x & (CC - 1); // % CC

    __shared__ unsigned cnt[NBKT];       // counts -> exclusive prefix (in place)
    __shared__ float    skey[NN];        // values in bucket order
    __shared__ unsigned sidx[NN];        // original row index in bucket order
    __shared__ unsigned wsum[32];

    const int t    = threadIdx.x;
    const int lane = t & 31;
    const int wid  = t >> 5;

    const float v  = x[(b * NN + t) * CC + c];  // long-latency, issued first
    cnt[t] = 0u;
    const int bk = bucket_of(v);
    __syncthreads();

    // ---- histogram; slot = within-bucket ordinal ----
    const unsigned slot = atomicAdd(&cnt[bk], 1u);
    __syncthreads();

    // ---- block exclusive prefix sum, 1 bucket per thread ----
    const unsigned cv = cnt[t];
    unsigned inc = cv;
    #pragma unroll
    for (int j = 1; j < 32; j <<= 1) {
        unsigned n = __shfl_up_sync(0xffffffffu, inc, j);
        if (lane >= j) inc += n;
    }
    if (lane == 31) wsum[wid] = inc;
    __syncthreads();
    if (wid == 0) {
        unsigned w  = wsum[lane];
        unsigned wi = w;
        #pragma unroll
        for (int j = 1; j < 32; j <<= 1) {
            unsigned n = __shfl_up_sync(0xffffffffu, wi, j);
            if (lane >= j) wi += n;
        }
        wsum[lane] = wi - w;             // exclusive warp offset
    }
    __syncthreads();
    cnt[t] = wsum[wid] + (inc - cv);     // exclusive prefix
    __syncthreads();

    // ---- scatter into bucket order ----
    const unsigned pos = cnt[bk] + slot;
    skey[pos] = v;
    sidx[pos] = (unsigned)t;
    __syncthreads();

    // ---- epilogue: thread t owns sorted position t ----
    const float    v2   = skey[t];
    const unsigned orig = sidx[t];

    const int b_lo = bucket_of(v2 - WINDOW);
    const int b_hi = bucket_of(v2 + WINDOW);

    const unsigned start = cnt[b_lo];
    const unsigned end   = (b_hi >= NBKT - 1) ? (unsigned)NN : cnt[b_hi + 1];

    const float a = 500.0f * v2;
    float sum = (float)start;            // lower buckets contribute exactly 1
    for (unsigned i = start; i < end; ++i) {
        const float th = fast_tanh(fmaf(-500.0f, skey[i], a));
        sum = fmaf(0.5f, th, sum + 0.5f);
    }

    out[(b * NN + orig) * CC + c] = sum * (1.0f / (float)NN);
}

extern "C" void kernel_launch(void* const* d_in, const int* in_sizes, int n_in,
                              void* d_out, int out_size)
{
    const float* x = (const float*)d_in[0];
    float* out = (float*)d_out;
    softrank_bucket2_kernel<<<BB * CC, NN>>>(x, out);
}

// round 7
// speedup vs baseline: 3.0664x; 3.0664x over previous
#include <cuda_runtime.h>

// SoftRank via bucket-histogram rank + windowed exact sigmoid.
// out[b,j,c] = (1/N) * sum_i sigmoid(1000*(x[b,j,c]-x[b,i,c]))
//
// Per (b,c) column (one CTA, 1024 threads):
//   1. histogram 1024 values into 1024 buckets over [-5,5] (smem atomics)
//   2. block exclusive prefix sum, 1 bucket/thread, sentinel cnt[1024]=N
//   3. scatter values into bucket order
//   4. thread evaluates its OWN element: rank term = prefix of lower buckets
//      (each contributes exactly 1 up to tanh-tail ~1e-4 absolute),
//      plus branchless tanh.approx scan of the bucket window
//      (saturation makes out-of-window scanned elements exact).

#define NN       1024
#define CC       16
#define BB       8
#define NBKT     1024
#define RANGE_LO (-5.0f)
#define INV_W    102.4f          // NBKT / 10.0
#define WINDOW   0.009f          // |1000*(v-s)|/2 <= 9 outside window

__device__ __forceinline__ float fast_tanh(float x) {
    float r;
    asm("tanh.approx.f32 %0, %1;" : "=f"(r) : "f"(x));
    return r;
}

__device__ __forceinline__ int bucket_of(float v) {
    int b = (int)((v - RANGE_LO) * INV_W);
    return min(max(b, 0), NBKT - 1);
}

__global__ __launch_bounds__(NN) void softrank_bucket3_kernel(
    const float* __restrict__ x, float* __restrict__ out)
{
    const int b = blockIdx.x >> 4;       // / CC
    const int c = blockIdx.x & (CC - 1); // % CC

    __shared__ unsigned cnt[NBKT + 1];   // counts -> exclusive prefix; [NBKT] = N sentinel
    __shared__ float    skey[NN];        // values in bucket order
    __shared__ unsigned wsum[32];

    const int t    = threadIdx.x;
    const int lane = t & 31;
    const int wid  = t >> 5;

    const float v = x[(b * NN + t) * CC + c];  // long-latency, issued first
    cnt[t] = 0u;
    const int bk = bucket_of(v);
    __syncthreads();

    // ---- histogram; slot = within-bucket ordinal ----
    const unsigned slot = atomicAdd(&cnt[bk], 1u);
    __syncthreads();

    // ---- block exclusive prefix sum, 1 bucket per thread ----
    const unsigned cv = cnt[t];
    unsigned inc = cv;
    #pragma unroll
    for (int j = 1; j < 32; j <<= 1) {
        unsigned n = __shfl_up_sync(0xffffffffu, inc, j);
        if (lane >= j) inc += n;
    }
    if (lane == 31) wsum[wid] = inc;
    __syncthreads();
    if (wid == 0) {
        unsigned w  = wsum[lane];
        unsigned wi = w;
        #pragma unroll
        for (int j = 1; j < 32; j <<= 1) {
            unsigned n = __shfl_up_sync(0xffffffffu, wi, j);
            if (lane >= j) wi += n;
        }
        wsum[lane] = wi - w;             // exclusive warp offset
    }
    __syncthreads();
    cnt[t] = wsum[wid] + (inc - cv);     // exclusive prefix
    if (t == 0) cnt[NBKT] = (unsigned)NN; // sentinel: end lookup is branchless
    __syncthreads();

    // ---- scatter into bucket order ----
    skey[cnt[bk] + slot] = v;
    __syncthreads();

    // ---- epilogue on own element ----
    const int b_lo = bucket_of(v - WINDOW);
    const int b_hi = bucket_of(v + WINDOW);

    const unsigned start = cnt[b_lo];
    const unsigned end   = cnt[b_hi + 1];

    const float a = 500.0f * v;
    float s0 = 0.0f, s1 = 0.0f;
    unsigned i = start;
    for (; i + 1 < end; i += 2) {        // 2-way ILP on LDS + MUFU
        s0 += fast_tanh(fmaf(-500.0f, skey[i],     a));
        s1 += fast_tanh(fmaf(-500.0f, skey[i + 1], a));
    }
    if (i < end)
        s0 += fast_tanh(fmaf(-500.0f, skey[i], a));

    const float sum = (float)start
                    + 0.5f * (float)(end - start)
                    + 0.5f * (s0 + s1);

    out[(b * NN + t) * CC + c] = sum * (1.0f / (float)NN);
}

extern "C" void kernel_launch(void* const* d_in, const int* in_sizes, int n_in,
                              void* d_out, int out_size)
{
    const float* x = (const float*)d_in[0];
    float* out = (float*)d_out;
    softrank_bucket3_kernel<<<BB * CC, NN>>>(x, out);
}